// round 2
// baseline (speedup 1.0000x reference)
#include <cuda_runtime.h>
#include <math.h>
#include <math_constants.h>

// Problem constants
#define BB    2
#define CC    256
#define NTOK  32768      // 32*32*32
#define SS    256
#define TDIM  512
#define NHD   8
#define HDIM  32

// ---------------- scratch (single __device__ array, no allocations) ----------------
#define OFF_H1    0                         // [B*S*256]      = 131072
#define OFF_KRAW  (OFF_H1   + 131072)       // [B*S*C]
#define OFF_VRAW  (OFF_KRAW + 131072)
#define OFF_PHASE (OFF_VRAW + 131072)
#define OFF_KROT  (OFF_PHASE+ 131072)       // [B,NH,S,HD]
#define OFF_VT    (OFF_KROT + 131072)
#define OFF_Q     (OFF_VT   + 131072)       // [B,N,C] = 16777216
#define OFF_AO    (OFF_Q    + 16777216)     // [B,N,C]
#define OFF_INVF  (OFF_AO   + 16777216)     // [32]
#define SCR_TOTAL (OFF_INVF + 32)

__device__ float g_scr[SCR_TOTAL];

// packed f32x2 helpers
#define FMA2(acc, a, b) asm("fma.rn.f32x2 %0, %1, %2, %0;" : "+l"(acc) : "l"(a), "l"(b))
__device__ __forceinline__ float2 u2f2(unsigned long long u) {
    float2 r;
    r.x = __uint_as_float((unsigned)(u & 0xffffffffull));
    r.y = __uint_as_float((unsigned)(u >> 32));
    return r;
}
typedef unsigned long long ull;

// ---------------- rope inverse-frequency table ----------------
__global__ void init_invf_kernel() {
    int d = threadIdx.x;
    if (d < 32) {
        float e;
        if (d < 10)       e = (float)(2 * (d % 5)) / 10.f;        // z section (zd=10)
        else if (d < 20)  e = (float)(2 * ((d - 10) % 5)) / 10.f; // y section (yd=10)
        else              e = (float)(2 * ((d - 20) % 6)) / 12.f; // x section (xd=12)
        g_scr[OFF_INVF + d] = powf(10000.f, -e);
    }
}

// ---------------- small GEMM body: BM=32, BN=64, BK=16, 256 thr, 2x4 micro ----------------
__device__ __forceinline__ void gemm32x64_body(const float* __restrict__ A,
                                               const float* __restrict__ W,
                                               const float* __restrict__ bias,
                                               float* __restrict__ Y,
                                               int K, int N, int act,
                                               int m0, int j0,
                                               float* As, float* Ws) {
    int t = threadIdx.x;
    int tx = t & 15, ty = t >> 4;
    float acc[2][4] = {};
    for (int k0 = 0; k0 < K; k0 += 16) {
        if (t < 128) {
            int m = t >> 2, kq = (t & 3) * 4;
            float4 av = *(const float4*)&A[(size_t)(m0 + m) * K + k0 + kq];
            As[(kq + 0) * 33 + m] = av.x;
            As[(kq + 1) * 33 + m] = av.y;
            As[(kq + 2) * 33 + m] = av.z;
            As[(kq + 3) * 33 + m] = av.w;
        }
        {
            int kk = t >> 4, j4 = (t & 15) * 4;
            *(float4*)&Ws[kk * 64 + j4] = *(const float4*)&W[(size_t)(k0 + kk) * N + j0 + j4];
        }
        __syncthreads();
        #pragma unroll
        for (int kk = 0; kk < 16; kk++) {
            float a0 = As[kk * 33 + ty * 2], a1 = As[kk * 33 + ty * 2 + 1];
            #pragma unroll
            for (int j = 0; j < 4; j++) {
                float w = Ws[kk * 64 + tx + 16 * j];
                acc[0][j] += a0 * w;
                acc[1][j] += a1 * w;
            }
        }
        __syncthreads();
    }
    #pragma unroll
    for (int j = 0; j < 4; j++) {
        int jj = j0 + tx + 16 * j;
        float bv = bias[jj];
        #pragma unroll
        for (int i = 0; i < 2; i++) {
            float v = acc[i][j] + bv;
            if (act) v = 0.5f * v * (1.f + erff(v * 0.70710678118654752f));  // exact GELU
            Y[(size_t)(m0 + ty * 2 + i) * N + jj] = v;
        }
    }
}

// fused 3-way text GEMM (k_w / v_w / m1_w all: M=512, K=512, N=256)
__global__ void text3_kernel(const float* __restrict__ text,
                             const float* __restrict__ kw, const float* __restrict__ kb,
                             const float* __restrict__ vw, const float* __restrict__ vb,
                             const float* __restrict__ m1w, const float* __restrict__ m1b) {
    __shared__ float As[16 * 33];
    __shared__ float Ws[16 * 64];
    const float *W, *bias;
    float* Y;
    int act = 0;
    if (blockIdx.z == 0)      { W = kw;  bias = kb;  Y = g_scr + OFF_KRAW; }
    else if (blockIdx.z == 1) { W = vw;  bias = vb;  Y = g_scr + OFF_VRAW; }
    else                      { W = m1w; bias = m1b; Y = g_scr + OFF_H1; act = 1; }
    gemm32x64_body(text, W, bias, Y, 512, 256, act, blockIdx.y * 32, blockIdx.x * 64, As, Ws);
}

// phase GEMM: H1[512,256] @ m2_w[256,256]
__global__ void phase_gemm_kernel(const float* __restrict__ m2w, const float* __restrict__ m2b) {
    __shared__ float As[16 * 33];
    __shared__ float Ws[16 * 64];
    gemm32x64_body(g_scr + OFF_H1, m2w, m2b, g_scr + OFF_PHASE, 256, 256, 0,
                   blockIdx.y * 32, blockIdx.x * 64, As, Ws);
}

// ---------------- text rope + [B,S,NH,HD] -> [B,NH,S,HD] transpose ----------------
__global__ void text_rope_kernel() {
    int idx = blockIdx.x * blockDim.x + threadIdx.x;  // < B*S*NH*16 = 65536
    int p = idx & 15;
    int h = (idx >> 4) & 7;
    int s = (idx >> 7) & 255;
    int b = idx >> 15;
    const float* kraw = g_scr + OFF_KRAW;
    const float* vraw = g_scr + OFF_VRAW;
    const float* ph   = g_scr + OFF_PHASE;
    float* krot = g_scr + OFF_KROT;
    float* vt   = g_scr + OFF_VT;
    int base = (b * SS + s) * CC + h * HDIM;
    int out  = ((b * NHD + h) * SS + s) * HDIM;
    float k0 = kraw[base + p], k1 = kraw[base + p + 16];
    float p0 = ph[base + p],   p1 = ph[base + p + 16];
    float c0, s0, c1, s1;
    sincosf(p0, &s0, &c0);
    sincosf(p1, &s1, &c1);
    krot[out + p]      = k0 * c0 - k1 * s0;
    krot[out + p + 16] = k1 * c1 + k0 * s1;
    vt[out + p]        = vraw[base + p];
    vt[out + p + 16]   = vraw[base + p + 16];
}

// ---------------- Q projection with fused 3D rope epilogue ----------------
// Q[b,n,j] = rope( sum_c fv[b,c,n] * W[c,j] + bias[j] ).
// 128x128x8 tile, 256 threads. Thread columns: c1 = h*32 + p + {0..3}, c2 = c1+16
// (both halves of every rope pair owned by the same thread).
// Inner loop: FFMA2 with i(token)-pairs packed, W duplicated in smem for LDS.64 (w,w).
__global__ void qproj_kernel(const float* __restrict__ A, const float* __restrict__ W,
                             const float* __restrict__ bias) {
    __shared__ float As[8 * 128];
    __shared__ float Wd[8 * 256];   // duplicated: Wd[k][2j] = Wd[k][2j+1] = W[k][j]
    float* Y = g_scr + OFF_Q;
    const float* invf = g_scr + OFF_INVF;
    int b = blockIdx.z;
    int n0 = blockIdx.y * 128, j0 = blockIdx.x * 128;
    int t = threadIdx.x;
    int tx = t & 15, ty = t >> 4;
    int hh = tx >> 2, p = (tx & 3) * 4;
    int c1 = hh * 32 + p, c2 = c1 + 16;
    const float* Ab = A + (size_t)b * CC * NTOK;
    ull acc[4][8] = {};
    int lk = t >> 5, lc = (t & 31) * 4;
    for (int k0 = 0; k0 < CC; k0 += 8) {
        *(float4*)&As[lk * 128 + lc] = *(const float4*)&Ab[(size_t)(k0 + lk) * NTOK + n0 + lc];
        {
            float4 w = *(const float4*)&W[(size_t)(k0 + lk) * CC + j0 + lc];
            *(float2*)&Wd[lk * 256 + 2 * lc + 0] = make_float2(w.x, w.x);
            *(float2*)&Wd[lk * 256 + 2 * lc + 2] = make_float2(w.y, w.y);
            *(float2*)&Wd[lk * 256 + 2 * lc + 4] = make_float2(w.z, w.z);
            *(float2*)&Wd[lk * 256 + 2 * lc + 6] = make_float2(w.w, w.w);
        }
        __syncthreads();
        #pragma unroll
        for (int kk = 0; kk < 8; kk++) {
            ulonglong2 a01 = *(ulonglong2*)&As[kk * 128 + ty * 4];
            ulonglong2 a23 = *(ulonglong2*)&As[kk * 128 + 64 + ty * 4];
            ull ap[4] = {a01.x, a01.y, a23.x, a23.y};
            ulonglong2 w01 = *(ulonglong2*)&Wd[kk * 256 + 2 * c1];
            ulonglong2 w23 = *(ulonglong2*)&Wd[kk * 256 + 2 * c1 + 4];
            ulonglong2 w45 = *(ulonglong2*)&Wd[kk * 256 + 2 * c2];
            ulonglong2 w67 = *(ulonglong2*)&Wd[kk * 256 + 2 * c2 + 4];
            ull wd[8] = {w01.x, w01.y, w23.x, w23.y, w45.x, w45.y, w67.x, w67.y};
            #pragma unroll
            for (int ip = 0; ip < 4; ip++)
                #pragma unroll
                for (int jj = 0; jj < 8; jj++)
                    FMA2(acc[ip][jj], ap[ip], wd[jj]);
        }
        __syncthreads();
    }
    // epilogue: bias + 3D rope, then store
    float b_lo[4], b_hi[4], if0[4], if1[4];
    #pragma unroll
    for (int jc = 0; jc < 4; jc++) {
        b_lo[jc] = bias[j0 + c1 + jc];
        b_hi[jc] = bias[j0 + c2 + jc];
        if0[jc] = invf[p + jc];
        if1[jc] = invf[p + jc + 16];
    }
    #pragma unroll
    for (int i = 0; i < 8; i++) {
        int mloc = (i < 4) ? (ty * 4 + i) : (64 + ty * 4 + (i - 4));
        int n = n0 + mloc;
        int wx = n & 31, hy = (n >> 5) & 31, dz = n >> 10;
        int ip = i >> 1, half = i & 1;
        float v1[4], v2[4];
        #pragma unroll
        for (int jc = 0; jc < 4; jc++) {
            float2 alo = u2f2(acc[ip][jc]);
            float2 ahi = u2f2(acc[ip][4 + jc]);
            float q0 = (half ? alo.y : alo.x) + b_lo[jc];
            float q1 = (half ? ahi.y : ahi.x) + b_hi[jc];
            int dd = p + jc;
            float pos0 = (dd < 10) ? (float)dz : (float)hy;
            float pos1 = (dd + 16 < 20) ? (float)hy : (float)wx;
            float f0 = pos0 * if0[jc], f1 = pos1 * if1[jc];
            float cs0, sn0, cs1, sn1;
            sincosf(f0, &sn0, &cs0);
            sincosf(f1, &sn1, &cs1);
            v1[jc] = q0 * cs0 - q1 * sn0;
            v2[jc] = q1 * cs1 + q0 * sn1;
        }
        float* yp = Y + ((size_t)b * NTOK + n) * CC;
        *(float4*)&yp[j0 + c1] = *(float4*)v1;
        *(float4*)&yp[j0 + c2] = *(float4*)v2;
    }
}

// ---------------- attention: per (b,h), 64 tokens/block, FFMA2 throughout ----------------
// smem: Qst[32][68] (d-major, scale folded), Ksd[32][512] (d-major, s duplicated),
//       Vsd[256][64] (s-major, d duplicated), Pt[256][68] ([s][m]), Pm/Psum[256]
#define ATT_SMEM_FLOATS (32*68 + 32*512 + 256*64 + 256*68 + 256 + 256)
__global__ void attn_kernel() {
    extern __shared__ float sm[];
    float* Qst  = sm;                  // [32][68]
    float* Ksd  = Qst + 32 * 68;       // [32][512]
    float* Vsd  = Ksd + 32 * 512;      // [256][64]
    float* Pt   = Vsd + 256 * 64;      // [256][68]
    float* Pm   = Pt + 256 * 68;       // [4][64]
    float* Psum = Pm + 256;            // [4][64]
    const float* q    = g_scr + OFF_Q;
    const float* krot = g_scr + OFF_KROT;
    const float* vt   = g_scr + OFF_VT;
    float* ao = g_scr + OFF_AO;
    int b = blockIdx.z, h = blockIdx.y;
    int n0 = blockIdx.x * 64;
    int t = threadIdx.x;
    const float scale = 0.17677669529663687f;  // 32^-0.5

    // pass 1: coalesced loads. K staged into Pt[s*33+d] (temp); V duplicated directly.
    size_t kvbase = (size_t)(b * NHD + h) * SS * HDIM;
    for (int idx = t; idx < 64 * 32; idx += 256) {
        int tok = idx >> 5, d = idx & 31;
        Qst[d * 68 + tok] = q[((size_t)b * NTOK + n0 + tok) * CC + h * HDIM + d] * scale;
    }
    for (int idx = t; idx < 256 * 32; idx += 256) {
        int s = idx >> 5, d = idx & 31;
        Pt[s * 33 + d] = krot[kvbase + idx];
        float vv = vt[kvbase + idx];
        *(float2*)&Vsd[s * 64 + 2 * d] = make_float2(vv, vv);
    }
    __syncthreads();
    // pass 2: build Ksd[d][2s] (duplicated, s-major) from staged K, conflict-free
    #pragma unroll 4
    for (int i = 0; i < 32; i++) {
        float kv = Pt[t * 33 + i];
        *(float2*)&Ksd[i * 512 + 2 * t] = make_float2(kv, kv);
    }
    __syncthreads();

    // Phase A: Pt[s][m] = (Q*scale) . K   via FFMA2 (token pairs x dup K)
    int tx4 = (t & 15) * 4, ty = t >> 4;
    #pragma unroll 1
    for (int sc = 0; sc < 4; sc++) {
        ull acc[2][4] = {};
        #pragma unroll 8
        for (int d = 0; d < 32; d++) {
            ulonglong2 qp = *(ulonglong2*)&Qst[d * 68 + ty * 4];
            ulonglong2 k01 = *(ulonglong2*)&Ksd[d * 512 + 2 * (sc * 64 + tx4)];
            ulonglong2 k23 = *(ulonglong2*)&Ksd[d * 512 + 2 * (sc * 64 + tx4) + 4];
            ull kd[4] = {k01.x, k01.y, k23.x, k23.y};
            #pragma unroll
            for (int jc = 0; jc < 4; jc++) {
                FMA2(acc[0][jc], qp.x, kd[jc]);
                FMA2(acc[1][jc], qp.y, kd[jc]);
            }
        }
        #pragma unroll
        for (int pp = 0; pp < 2; pp++)
            #pragma unroll
            for (int jc = 0; jc < 4; jc++)
                *(float2*)&Pt[(sc * 64 + tx4 + jc) * 68 + ty * 4 + 2 * pp] = u2f2(acc[pp][jc]);
    }
    __syncthreads();

    // Softmax over s: thread owns (row m = t&63, quarter qd = t>>6); Z folded into phase B
    {
        int m = t & 63, qd = t >> 6;
        float mx = -CUDART_INF_F;
        #pragma unroll 4
        for (int k = 0; k < 64; k++) mx = fmaxf(mx, Pt[(qd * 64 + k) * 68 + m]);
        Pm[qd * 64 + m] = mx;
        __syncthreads();
        float rmx = fmaxf(fmaxf(Pm[m], Pm[64 + m]), fmaxf(Pm[128 + m], Pm[192 + m]));
        float lsum = 0.f;
        #pragma unroll 4
        for (int k = 0; k < 64; k++) {
            float e = __expf(Pt[(qd * 64 + k) * 68 + m] - rmx);
            Pt[(qd * 64 + k) * 68 + m] = e;
            lsum += e;
        }
        Psum[qd * 64 + m] = lsum;
    }
    __syncthreads();

    // Phase B: O[64 x 32] = P @ V via FFMA2 (token pairs x dup V)
    {
        int d = t & 31, mg = t >> 5;
        ull o[4] = {};
        #pragma unroll 2
        for (int s = 0; s < 256; s++) {
            ulonglong2 p01 = *(ulonglong2*)&Pt[s * 68 + mg * 8];
            ulonglong2 p23 = *(ulonglong2*)&Pt[s * 68 + mg * 8 + 4];
            ull vv = *(ull*)&Vsd[s * 64 + 2 * d];
            FMA2(o[0], p01.x, vv);
            FMA2(o[1], p01.y, vv);
            FMA2(o[2], p23.x, vv);
            FMA2(o[3], p23.y, vv);
        }
        #pragma unroll
        for (int qq = 0; qq < 4; qq++) {
            float2 f = u2f2(o[qq]);
            int m = mg * 8 + 2 * qq;
            float Z0 = Psum[m] + Psum[64 + m] + Psum[128 + m] + Psum[192 + m];
            float Z1 = Psum[m + 1] + Psum[64 + m + 1] + Psum[128 + m + 1] + Psum[192 + m + 1];
            ao[((size_t)b * NTOK + n0 + m) * CC + h * HDIM + d]     = f.x / Z0;
            ao[((size_t)b * NTOK + n0 + m + 1) * CC + h * HDIM + d] = f.y / Z1;
        }
    }
}

// ---------------- O projection + transpose, FFMA2 ----------------
__global__ void oproj_kernel(const float* __restrict__ W, const float* __restrict__ bias,
                             float* __restrict__ Out) {
    __shared__ float As[8 * 132];   // transposed on load
    __shared__ float Wd[8 * 256];   // duplicated
    const float* Ain = g_scr + OFF_AO;
    int b = blockIdx.z;
    int n0 = blockIdx.y * 128, j0 = blockIdx.x * 128;
    int t = threadIdx.x;
    int tx = t & 15, ty = t >> 4;
    int c1 = tx * 4, c2 = 64 + tx * 4;
    ull acc[4][8] = {};
    int lm = t >> 1, lkq = (t & 1) * 4;
    int lk = t >> 5, lc = (t & 31) * 4;
    for (int k0 = 0; k0 < CC; k0 += 8) {
        float4 av = *(const float4*)&Ain[((size_t)b * NTOK + n0 + lm) * CC + k0 + lkq];
        As[(lkq + 0) * 132 + lm] = av.x;
        As[(lkq + 1) * 132 + lm] = av.y;
        As[(lkq + 2) * 132 + lm] = av.z;
        As[(lkq + 3) * 132 + lm] = av.w;
        {
            float4 w = *(const float4*)&W[(size_t)(k0 + lk) * CC + j0 + lc];
            *(float2*)&Wd[lk * 256 + 2 * lc + 0] = make_float2(w.x, w.x);
            *(float2*)&Wd[lk * 256 + 2 * lc + 2] = make_float2(w.y, w.y);
            *(float2*)&Wd[lk * 256 + 2 * lc + 4] = make_float2(w.z, w.z);
            *(float2*)&Wd[lk * 256 + 2 * lc + 6] = make_float2(w.w, w.w);
        }
        __syncthreads();
        #pragma unroll
        for (int kk = 0; kk < 8; kk++) {
            ulonglong2 a01 = *(ulonglong2*)&As[kk * 132 + ty * 4];
            ulonglong2 a23 = *(ulonglong2*)&As[kk * 132 + 64 + ty * 4];
            ull ap[4] = {a01.x, a01.y, a23.x, a23.y};
            ulonglong2 w01 = *(ulonglong2*)&Wd[kk * 256 + 2 * c1];
            ulonglong2 w23 = *(ulonglong2*)&Wd[kk * 256 + 2 * c1 + 4];
            ulonglong2 w45 = *(ulonglong2*)&Wd[kk * 256 + 2 * c2];
            ulonglong2 w67 = *(ulonglong2*)&Wd[kk * 256 + 2 * c2 + 4];
            ull wd[8] = {w01.x, w01.y, w23.x, w23.y, w45.x, w45.y, w67.x, w67.y};
            #pragma unroll
            for (int ip = 0; ip < 4; ip++)
                #pragma unroll
                for (int jj = 0; jj < 8; jj++)
                    FMA2(acc[ip][jj], ap[ip], wd[jj]);
        }
        __syncthreads();
    }
    #pragma unroll
    for (int jj = 0; jj < 8; jj++) {
        int col = j0 + ((jj < 4) ? (c1 + jj) : (c2 + jj - 4));
        float bv = bias[col];
        float2 f0 = u2f2(acc[0][jj]);
        float2 f1 = u2f2(acc[1][jj]);
        float2 f2 = u2f2(acc[2][jj]);
        float2 f3 = u2f2(acc[3][jj]);
        float4 v1 = make_float4(f0.x + bv, f0.y + bv, f1.x + bv, f1.y + bv);
        float4 v2 = make_float4(f2.x + bv, f2.y + bv, f3.x + bv, f3.y + bv);
        float* outp = Out + (size_t)b * CC * NTOK + (size_t)col * NTOK;
        *(float4*)&outp[n0 + ty * 4]      = v1;
        *(float4*)&outp[n0 + 64 + ty * 4] = v2;
    }
}

// ---------------- launch ----------------
extern "C" void kernel_launch(void* const* d_in, const int* in_sizes, int n_in,
                              void* d_out, int out_size) {
    const float* fv   = (const float*)d_in[0];
    const float* text = (const float*)d_in[1];
    const float* q_w  = (const float*)d_in[2];
    const float* q_b  = (const float*)d_in[3];
    const float* k_w  = (const float*)d_in[4];
    const float* k_b  = (const float*)d_in[5];
    const float* v_w  = (const float*)d_in[6];
    const float* v_b  = (const float*)d_in[7];
    const float* o_w  = (const float*)d_in[8];
    const float* o_b  = (const float*)d_in[9];
    const float* m1_w = (const float*)d_in[10];
    const float* m1_b = (const float*)d_in[11];
    const float* m2_w = (const float*)d_in[12];
    const float* m2_b = (const float*)d_in[13];
    float* out = (float*)d_out;

    init_invf_kernel<<<1, 32>>>();

    // Text side
    text3_kernel<<<dim3(4, 16, 3), 256>>>(text, k_w, k_b, v_w, v_b, m1_w, m1_b);
    phase_gemm_kernel<<<dim3(4, 16), 256>>>(m2_w, m2_b);
    text_rope_kernel<<<256, 256>>>();

    // Visual side: Q projection with fused rope
    qproj_kernel<<<dim3(2, 256, 2), 256>>>(fv, q_w, q_b);

    cudaFuncSetAttribute(attn_kernel, cudaFuncAttributeMaxDynamicSharedMemorySize,
                         ATT_SMEM_FLOATS * (int)sizeof(float));
    attn_kernel<<<dim3(512, 8, 2), 256, ATT_SMEM_FLOATS * sizeof(float)>>>();

    oproj_kernel<<<dim3(2, 256, 2), 256>>>(o_w, o_b, out);
}